// round 3
// baseline (speedup 1.0000x reference)
#include <cuda_runtime.h>
#include <cuda_bf16.h>
#include <cstdint>

// B=2, S=512, D=256, N=16, DC=4, DI=512, CHUNK=32, rows=1024

// ---------------- scratch ----------------
__device__ __nv_bfloat16 g_xnb [1024*256];
__device__ __nv_bfloat16 g_xpb [1024*512];
__device__ float         g_sz  [1024*512];
__device__ float         g_xact[1024*512];
__device__ float         g_decay[1024*512];
__device__ __nv_bfloat16 g_Bmb [1024*16];
__device__ __nv_bfloat16 g_Cmb [1024*16];
__device__ float         g_invdeg[1024];
__device__ float         g_any [1024];
__device__ float         g_condT[512];
__device__ __nv_bfloat16 g_Pb  [1024*512];
__device__ __nv_bfloat16 g_Winb [1024*256];
__device__ __nv_bfloat16 g_Woutb[256*512];
__device__ __nv_bfloat16 g_adjb [2*512*512];
__device__ __nv_bfloat16 g_cwb  [4*512*512];   // [kc][n][k]

// ---------------- mma helpers ----------------
__device__ __forceinline__ uint32_t smem_u32(const void* p) {
    return (uint32_t)__cvta_generic_to_shared(p);
}
__device__ __forceinline__ void ldsm_x4(uint32_t* r, uint32_t a) {
    asm volatile("ldmatrix.sync.aligned.m8n8.x4.shared.b16 {%0,%1,%2,%3}, [%4];\n"
                 : "=r"(r[0]), "=r"(r[1]), "=r"(r[2]), "=r"(r[3]) : "r"(a));
}
__device__ __forceinline__ void ldsm_x4t(uint32_t* r, uint32_t a) {
    asm volatile("ldmatrix.sync.aligned.m8n8.x4.trans.shared.b16 {%0,%1,%2,%3}, [%4];\n"
                 : "=r"(r[0]), "=r"(r[1]), "=r"(r[2]), "=r"(r[3]) : "r"(a));
}
__device__ __forceinline__ void mma_bf16(float* c, const uint32_t* a, const uint32_t* b) {
    asm volatile(
        "mma.sync.aligned.m16n8k16.row.col.f32.bf16.bf16.f32 "
        "{%0,%1,%2,%3}, {%4,%5,%6,%7}, {%8,%9}, {%0,%1,%2,%3};\n"
        : "+f"(c[0]), "+f"(c[1]), "+f"(c[2]), "+f"(c[3])
        : "r"(a[0]), "r"(a[1]), "r"(a[2]), "r"(a[3]), "r"(b[0]), "r"(b[1]));
}

// ---------------- conversions ----------------
__global__ void cvt_misc(const float* __restrict__ W_in,
                         const float* __restrict__ W_out,
                         const float* __restrict__ adj) {
    const int n1 = 1024 * 256, n2 = 256 * 512, n3 = 2 * 512 * 512;
    for (int i = blockIdx.x * blockDim.x + threadIdx.x; i < n1 + n2 + n3;
         i += gridDim.x * blockDim.x) {
        if (i < n1) g_Winb[i] = __float2bfloat16(W_in[i]);
        else if (i < n1 + n2) g_Woutb[i - n1] = __float2bfloat16(W_out[i - n1]);
        else g_adjb[i - n1 - n2] = __float2bfloat16(adj[i - n1 - n2]);
    }
}
__global__ void cvt_convw(const float* __restrict__ conv_w) {
    for (int i = blockIdx.x * blockDim.x + threadIdx.x; i < 4 * 512 * 512;
         i += gridDim.x * blockDim.x) {
        int kc = i >> 18, n = (i >> 9) & 511, k = i & 511;
        g_cwb[i] = __float2bfloat16(conv_w[n * 2048 + k * 4 + kc]);
    }
}

// ---------------- LayerNorm -> bf16 ----------------
__global__ void __launch_bounds__(256) ln_kernel(const float* __restrict__ x,
                                                 const float* __restrict__ lw,
                                                 const float* __restrict__ lb) {
    __shared__ float red[256];
    int row = blockIdx.x, t = threadIdx.x;
    float v = x[row * 256 + t];
    red[t] = v; __syncthreads();
    for (int s = 128; s > 0; s >>= 1) { if (t < s) red[t] += red[t + s]; __syncthreads(); }
    float mu = red[0] * (1.0f / 256.0f); __syncthreads();
    float dv = v - mu;
    red[t] = dv * dv; __syncthreads();
    for (int s = 128; s > 0; s >>= 1) { if (t < s) red[t] += red[t + s]; __syncthreads(); }
    float var = red[0] * (1.0f / 256.0f);
    g_xnb[row * 256 + t] = __float2bfloat16(dv * rsqrtf(var + 1e-5f) * lw[t] + lb[t]);
}

// ---------------- MMA GEMM core (64x64 tile, 128 thr, warps 2x2) ----------------
#define MMA_TILE_BODY(A_LOAD, W_LOAD)                                            \
    __shared__ __align__(16) __nv_bfloat16 As[64][16];                           \
    __shared__ __align__(16) __nv_bfloat16 Ws[64][16];                           \
    int tid = threadIdx.x, lane = tid & 31, wid = tid >> 5;                      \
    int wr = wid >> 1, wc = wid & 1;                                             \
    int srow = tid >> 1, shalf = tid & 1;                                        \
    float cfr[2][4][4] = {};                                                     \
    int ar = wr * 32 + (lane & 15), ac = (lane >> 4) * 8;                        \
    int br_ = wc * 32 + (lane & 7) + ((lane >> 4) * 8), bc = ((lane >> 3) & 1) * 8;

#define MMA_KSTEP()                                                              \
    do {                                                                         \
        __syncthreads();                                                         \
        uint32_t afr[2][4], bfr[2][4];                                           \
        ldsm_x4(afr[0], smem_u32(&As[ar][ac]));                                  \
        ldsm_x4(afr[1], smem_u32(&As[ar + 16][ac]));                             \
        ldsm_x4(bfr[0], smem_u32(&Ws[br_][bc]));                                 \
        ldsm_x4(bfr[1], smem_u32(&Ws[br_ + 16][bc]));                            \
        _Pragma("unroll")                                                        \
        for (int mt = 0; mt < 2; ++mt) {                                         \
            mma_bf16(cfr[mt][0], afr[mt], bfr[0] + 0);                           \
            mma_bf16(cfr[mt][1], afr[mt], bfr[0] + 2);                           \
            mma_bf16(cfr[mt][2], afr[mt], bfr[1] + 0);                           \
            mma_bf16(cfr[mt][3], afr[mt], bfr[1] + 2);                           \
        }                                                                        \
        __syncthreads();                                                         \
    } while (0)

// xz = xn @ W_in^T ; split xp(bf16) / silu(z)(fp32)
__global__ void __launch_bounds__(128) gemm_xz() {
    int m0 = blockIdx.y * 64, n0 = blockIdx.x * 64;
    MMA_TILE_BODY(,)
    for (int k0 = 0; k0 < 256; k0 += 16) {
        *(uint4*)&As[srow][shalf * 8] = *(const uint4*)&g_xnb[(m0 + srow) * 256 + k0 + shalf * 8];
        *(uint4*)&Ws[srow][shalf * 8] = *(const uint4*)&g_Winb[(n0 + srow) * 256 + k0 + shalf * 8];
        MMA_KSTEP();
    }
    int gr = lane >> 2, tc2 = (lane & 3) * 2;
#pragma unroll
    for (int mt = 0; mt < 2; ++mt)
#pragma unroll
        for (int nt = 0; nt < 4; ++nt)
#pragma unroll
            for (int e = 0; e < 4; ++e) {
                int m = m0 + wr * 32 + mt * 16 + gr + ((e >> 1) * 8);
                int n = n0 + wc * 32 + nt * 8 + tc2 + (e & 1);
                float v = cfr[mt][nt][e];
                if (n < 512) g_xpb[m * 512 + n] = __float2bfloat16(v);
                else         g_sz[m * 512 + (n - 512)] = v / (1.0f + __expf(-v));
            }
}

// xact = silu(conv(xp)+b): 4 shifted GEMM passes
__global__ void __launch_bounds__(128) gemm_conv(const float* __restrict__ conv_b) {
    int m0 = blockIdx.y * 64, n0 = blockIdx.x * 64;
    MMA_TILE_BODY(,)
    for (int kc = 0; kc < 4; ++kc) {
        int tsrc = ((m0 + srow) & 511) - 3 + kc;
        const __nv_bfloat16* arow = g_xpb + (long long)(m0 + srow - 3 + kc) * 512;
        const __nv_bfloat16* wbase = g_cwb + kc * 262144;
        for (int k0 = 0; k0 < 512; k0 += 16) {
            uint4 av = make_uint4(0u, 0u, 0u, 0u);
            if (tsrc >= 0) av = *(const uint4*)(arow + k0 + shalf * 8);
            *(uint4*)&As[srow][shalf * 8] = av;
            *(uint4*)&Ws[srow][shalf * 8] = *(const uint4*)&wbase[(n0 + srow) * 512 + k0 + shalf * 8];
            MMA_KSTEP();
        }
    }
    int gr = lane >> 2, tc2 = (lane & 3) * 2;
#pragma unroll
    for (int mt = 0; mt < 2; ++mt)
#pragma unroll
        for (int nt = 0; nt < 4; ++nt)
#pragma unroll
            for (int e = 0; e < 4; ++e) {
                int m = m0 + wr * 32 + mt * 16 + gr + ((e >> 1) * 8);
                int n = n0 + wc * 32 + nt * 8 + tc2 + (e & 1);
                float v = cfr[mt][nt][e] + conv_b[n];
                g_xact[m * 512 + n] = v / (1.0f + __expf(-v));
            }
}

// out = P @ W_out^T + x
__global__ void __launch_bounds__(128) gemm_out(const float* __restrict__ x,
                                                float* __restrict__ out) {
    int m0 = blockIdx.y * 64, n0 = blockIdx.x * 64;
    MMA_TILE_BODY(,)
    for (int k0 = 0; k0 < 512; k0 += 16) {
        *(uint4*)&As[srow][shalf * 8] = *(const uint4*)&g_Pb[(m0 + srow) * 512 + k0 + shalf * 8];
        *(uint4*)&Ws[srow][shalf * 8] = *(const uint4*)&g_Woutb[(n0 + srow) * 512 + k0 + shalf * 8];
        MMA_KSTEP();
    }
    int gr = lane >> 2, tc2 = (lane & 3) * 2;
#pragma unroll
    for (int mt = 0; mt < 2; ++mt)
#pragma unroll
        for (int nt = 0; nt < 4; ++nt)
#pragma unroll
            for (int e = 0; e < 4; ++e) {
                int m = m0 + wr * 32 + mt * 16 + gr + ((e >> 1) * 8);
                int n = n0 + wc * 32 + nt * 8 + tc2 + (e & 1);
                out[m * 256 + n] = cfr[mt][nt][e] + x[m * 256 + n];
            }
}

// ---------------- ssm ----------------
__global__ void __launch_bounds__(128) ssm_kernel(const float* __restrict__ W_xp,
                                                  const float* __restrict__ W_dt,
                                                  const float* __restrict__ b_dt) {
    __shared__ float xs[512];
    __shared__ float ssm_sh[33];
    int row = blockIdx.x, tid = threadIdx.x, lane = tid & 31, wid = tid >> 5;
    for (int i = tid; i < 512; i += 128) xs[i] = g_xact[row * 512 + i];
    __syncthreads();
    for (int o = wid; o < 33; o += 4) {
        float p = 0.f;
        for (int i = lane; i < 512; i += 32) p += xs[i] * W_xp[o * 512 + i];
        for (int k = 16; k > 0; k >>= 1) p += __shfl_xor_sync(0xffffffffu, p, k);
        if (lane == 0) ssm_sh[o] = p;
    }
    __syncthreads();
    if (tid < 16) {
        g_Bmb[row * 16 + tid] = __float2bfloat16(ssm_sh[1 + tid]);
        g_Cmb[row * 16 + tid] = __float2bfloat16(ssm_sh[17 + tid]);
    }
    float s0 = ssm_sh[0];
    for (int d = tid; d < 512; d += 128) {
        float v = s0 * W_dt[d] + b_dt[d];
        g_decay[row * 512 + d] = 1.0f / (1.0f + expf(v));  // exp(-softplus(v))
    }
}

// ---------------- deg / cond ----------------
__global__ void __launch_bounds__(256) deg_kernel(const float* __restrict__ adj) {
    __shared__ float rs[256];
    __shared__ int   ra[256];
    int row = blockIdx.x, b = row >> 9, t = row & 511;
    const float* a = adj + (size_t)(b * 512 + t) * 512;
    float s = 0.f; int any = 0;
    for (int i = threadIdx.x; i < t; i += 256) { float v = a[i]; s += v; any |= (v > 0.f); }
    rs[threadIdx.x] = s; ra[threadIdx.x] = any; __syncthreads();
    for (int k = 128; k > 0; k >>= 1) {
        if (threadIdx.x < k) { rs[threadIdx.x] += rs[threadIdx.x + k]; ra[threadIdx.x] |= ra[threadIdx.x + k]; }
        __syncthreads();
    }
    if (threadIdx.x == 0) {
        g_invdeg[row] = 1.0f / fmaxf(rs[0], 1.0f);
        g_any[row] = ra[0] ? 1.f : 0.f;
    }
}
__global__ void cond_kernel() {
    int t = blockIdx.x * blockDim.x + threadIdx.x;
    if (t < 512) g_condT[t] = (t > 0 && (g_any[t] > 0.f || g_any[512 + t] > 0.f)) ? 1.f : 0.f;
}

// ---------------- scan: per-(b,d) block; MMA Gpre + warp0 sequential ----------------
__global__ void __launch_bounds__(128) scan_kernel(const float* __restrict__ Wr,
                                                   const float* __restrict__ br) {
    __shared__ __align__(16) __nv_bfloat16 hist[512][16];      // 16 KB
    __shared__ __align__(16) unsigned char ubuf[8192];         // adjS[4][32][32] bf16 | Gpart[4][32][16] f32
    __shared__ __align__(16) float Gsh[32][16];                // 2 KB
    __shared__ __align__(16) __nv_bfloat16 adjC[32][32];       // 2 KB
    __shared__ __align__(16) __nv_bfloat16 Bs[32][16], Cs[32][16];
    __shared__ float dec_s[32], xa_s[32], ivd_s[32], cond_s[32];
    __shared__ float Wr_s[16][17];
    __shared__ float br_s[16];
    __shared__ __align__(16) float h_sh[16];

#define ADJS(t_) ((__nv_bfloat16(*)[32])(ubuf + (t_) * 2048))
#define GPART(w_) ((float(*)[16])(ubuf + (w_) * 2048))

    int tid = threadIdx.x, lane = tid & 31, wid = tid >> 5;
    int seq = blockIdx.x, b = seq >> 9, d = seq & 511;
    const long long badj = (long long)b * 512 * 512;

    for (int i = tid; i < 256; i += 128) Wr_s[i >> 4][i & 15] = Wr[i];
    if (tid < 16) br_s[tid] = br[tid];

    float hreg = 0.0f;  // warp0 lanes 0..15

    for (int c = 0; c < 16; ++c) {
        int c0 = c << 5;
        __syncthreads();  // protect prev-chunk reads (warp0) vs new staging

        // ---- stage chunk-local arrays ----
        if (tid < 32) {
            int row = b * 512 + c0 + tid;
            dec_s[tid]  = g_decay[row * 512 + d];
            xa_s[tid]   = g_xact [row * 512 + d];
            ivd_s[tid]  = g_invdeg[row];
            cond_s[tid] = g_condT[c0 + tid];
        }
        if (tid < 64) {
            int r = tid >> 1, hh = tid & 1;
            *(uint4*)&Bs[r][hh * 8] = *(const uint4*)&g_Bmb[(b * 512 + c0 + r) * 16 + hh * 8];
        } else {
            int t2 = tid - 64, r = t2 >> 1, hh = t2 & 1;
            *(uint4*)&Cs[r][hh * 8] = *(const uint4*)&g_Cmb[(b * 512 + c0 + r) * 16 + hh * 8];
        }
        {
            int tt = tid >> 2, q = tid & 3;
            *(uint4*)&adjC[tt][q * 8] = *(const uint4*)&g_adjb[badj + (long long)(c0 + tt) * 512 + c0 + q * 8];
        }

        // ---- Gpre via tensor cores: groups of 4 st-tiles, one per warp ----
        float cfr[2][2][4] = {};
        for (int gbase = 0; gbase < c; gbase += 4) {
            __syncthreads();
            for (int e = tid; e < 512; e += 128) {  // 4 tiles * 128 uint4
                int tile = e >> 7, rem = e & 127, tt = rem >> 2, q = rem & 3;
                int st = gbase + tile;
                *(uint4*)&ADJS(tile)[tt][q * 8] =
                    *(const uint4*)&g_adjb[badj + (long long)(c0 + tt) * 512 + st * 32 + q * 8];
            }
            __syncthreads();
            int st = gbase + wid;
            if (st < c) {
                int sb = st << 5;
                uint32_t afr[4], bfr[4];
#pragma unroll
                for (int kt = 0; kt < 2; ++kt) {
                    ldsm_x4t(bfr, smem_u32(&hist[sb + kt * 16 + (lane & 15)][(lane >> 4) * 8]));
#pragma unroll
                    for (int mt = 0; mt < 2; ++mt) {
                        ldsm_x4(afr, smem_u32(&ADJS(wid)[mt * 16 + (lane & 15)][kt * 16 + (lane >> 4) * 8]));
                        mma_bf16(cfr[mt][0], afr, bfr + 0);
                        mma_bf16(cfr[mt][1], afr, bfr + 2);
                    }
                }
            }
        }
        __syncthreads();  // adjS reads done -> reuse as Gpart
        {
            int gr = lane >> 2, tc2 = (lane & 3) * 2;
#pragma unroll
            for (int mt = 0; mt < 2; ++mt)
#pragma unroll
                for (int nt = 0; nt < 2; ++nt) {
                    GPART(wid)[mt * 16 + gr][nt * 8 + tc2]         = cfr[mt][nt][0];
                    GPART(wid)[mt * 16 + gr][nt * 8 + tc2 + 1]     = cfr[mt][nt][1];
                    GPART(wid)[mt * 16 + gr + 8][nt * 8 + tc2]     = cfr[mt][nt][2];
                    GPART(wid)[mt * 16 + gr + 8][nt * 8 + tc2 + 1] = cfr[mt][nt][3];
                }
        }
        __syncthreads();
        for (int e = tid; e < 512; e += 128) {
            int t = e >> 4, n = e & 15;
            Gsh[t][n] = GPART(0)[t][n] + GPART(1)[t][n] + GPART(2)[t][n] + GPART(3)[t][n];
        }
        __syncthreads();

        // ---- sequential 32 steps: warp 0 only, no block barriers ----
        if (wid == 0) {
            for (int j = 0; j < 32; ++j) {
                if (lane < 16) {
                    float gv = Gsh[j][lane] * ivd_s[j];
                    float accb = br_s[lane];
#pragma unroll
                    for (int m = 0; m < 16; ++m)
                        accb += Wr_s[lane][m] * __shfl_sync(0x0000ffffu, gv, m, 16);
                    float bo = 0.1f * accb / (1.0f + __expf(-accb));
                    float h = hreg * dec_s[j] + xa_s[j] * __bfloat162float(Bs[j][lane])
                              + cond_s[j] * bo;
                    hreg = h;
                    h_sh[lane] = h;
                    hist[c0 + j][lane] = __float2bfloat16(h);
                    float y = h * __bfloat162float(Cs[j][lane]);
                    y += __shfl_xor_sync(0x0000ffffu, y, 8, 16);
                    y += __shfl_xor_sync(0x0000ffffu, y, 4, 16);
                    y += __shfl_xor_sync(0x0000ffffu, y, 2, 16);
                    y += __shfl_xor_sync(0x0000ffffu, y, 1, 16);
                    if (lane == 0) {
                        int row = b * 512 + c0 + j;
                        g_Pb[row * 512 + d] = __float2bfloat16(y * g_sz[row * 512 + d]);
                    }
                }
                __syncwarp();
                int q = lane & 3;
                for (int t = j + 1 + (lane >> 2); t < 32; t += 8) {
                    float a = __bfloat162float(adjC[t][j]);
                    float4 g = *(float4*)&Gsh[t][q * 4];
                    float4 hq = *(const float4*)&h_sh[q * 4];
                    g.x += a * hq.x; g.y += a * hq.y; g.z += a * hq.z; g.w += a * hq.w;
                    *(float4*)&Gsh[t][q * 4] = g;
                }
                __syncwarp();
            }
        }
    }
#undef ADJS
#undef GPART
}

// ---------------- launch ----------------
extern "C" void kernel_launch(void* const* d_in, const int* in_sizes, int n_in,
                              void* d_out, int out_size) {
    const float* x      = (const float*)d_in[0];
    const float* adj    = (const float*)d_in[1];
    const float* ln_w   = (const float*)d_in[2];
    const float* ln_b   = (const float*)d_in[3];
    const float* W_in   = (const float*)d_in[4];
    const float* conv_w = (const float*)d_in[5];
    const float* conv_b = (const float*)d_in[6];
    const float* W_xp   = (const float*)d_in[7];
    const float* W_dt   = (const float*)d_in[8];
    const float* b_dt   = (const float*)d_in[9];
    const float* Wr     = (const float*)d_in[10];
    const float* br     = (const float*)d_in[11];
    const float* W_out  = (const float*)d_in[12];
    float* out = (float*)d_out;

    cvt_misc<<<1024, 256>>>(W_in, W_out, adj);
    cvt_convw<<<1024, 256>>>(conv_w);
    ln_kernel<<<1024, 256>>>(x, ln_w, ln_b);
    gemm_xz<<<dim3(16, 16), 128>>>();
    deg_kernel<<<1024, 256>>>(adj);
    cond_kernel<<<2, 256>>>();
    gemm_conv<<<dim3(8, 16), 128>>>(conv_b);
    ssm_kernel<<<1024, 128>>>(W_xp, W_dt, b_dt);
    scan_kernel<<<1024, 128>>>(Wr, br);
    gemm_out<<<dim3(4, 16), 128>>>(x, out);
}

// round 4
// speedup vs baseline: 2.2786x; 2.2786x over previous
#include <cuda_runtime.h>
#include <cuda_bf16.h>
#include <cstdint>

// B=2, S=512, D=256, N=16, DC=4, DI=512, CHUNK=32, rows=1024

// ---------------- scratch ----------------
__device__ __nv_bfloat16 g_xnb [1024*256];
__device__ __nv_bfloat16 g_xpb [1024*512];
__device__ float         g_sz  [1024*512];
__device__ float         g_xact[1024*512];
__device__ float         g_decay[1024*512];
__device__ __nv_bfloat16 g_Bmb [1024*16];
__device__ __nv_bfloat16 g_Cmb [1024*16];
__device__ float         g_invdeg[1024];
__device__ float         g_any [1024];
__device__ float         g_condT[512];
__device__ __nv_bfloat16 g_Pb  [1024*512];
__device__ __nv_bfloat16 g_Winb [1024*256];
__device__ __nv_bfloat16 g_Woutb[256*512];
__device__ __nv_bfloat16 g_adjb [2*512*512];
__device__ __nv_bfloat16 g_cwb  [4*512*512];   // [kc][n][k]

// ---------------- mma helpers ----------------
__device__ __forceinline__ uint32_t smem_u32(const void* p) {
    return (uint32_t)__cvta_generic_to_shared(p);
}
__device__ __forceinline__ void ldsm_x4(uint32_t* r, uint32_t a) {
    asm volatile("ldmatrix.sync.aligned.m8n8.x4.shared.b16 {%0,%1,%2,%3}, [%4];\n"
                 : "=r"(r[0]), "=r"(r[1]), "=r"(r[2]), "=r"(r[3]) : "r"(a));
}
__device__ __forceinline__ void ldsm_x4t(uint32_t* r, uint32_t a) {
    asm volatile("ldmatrix.sync.aligned.m8n8.x4.trans.shared.b16 {%0,%1,%2,%3}, [%4];\n"
                 : "=r"(r[0]), "=r"(r[1]), "=r"(r[2]), "=r"(r[3]) : "r"(a));
}
__device__ __forceinline__ void mma_bf16(float* c, const uint32_t* a, const uint32_t* b) {
    asm volatile(
        "mma.sync.aligned.m16n8k16.row.col.f32.bf16.bf16.f32 "
        "{%0,%1,%2,%3}, {%4,%5,%6,%7}, {%8,%9}, {%0,%1,%2,%3};\n"
        : "+f"(c[0]), "+f"(c[1]), "+f"(c[2]), "+f"(c[3])
        : "r"(a[0]), "r"(a[1]), "r"(a[2]), "r"(a[3]), "r"(b[0]), "r"(b[1]));
}

// ---------------- conversions ----------------
__global__ void cvt_misc(const float* __restrict__ W_in,
                         const float* __restrict__ W_out,
                         const float* __restrict__ adj) {
    const int n1 = 1024 * 256, n2 = 256 * 512, n3 = 2 * 512 * 512;
    for (int i = blockIdx.x * blockDim.x + threadIdx.x; i < n1 + n2 + n3;
         i += gridDim.x * blockDim.x) {
        if (i < n1) g_Winb[i] = __float2bfloat16(W_in[i]);
        else if (i < n1 + n2) g_Woutb[i - n1] = __float2bfloat16(W_out[i - n1]);
        else g_adjb[i - n1 - n2] = __float2bfloat16(adj[i - n1 - n2]);
    }
}
__global__ void cvt_convw(const float* __restrict__ conv_w) {
    for (int i = blockIdx.x * blockDim.x + threadIdx.x; i < 4 * 512 * 512;
         i += gridDim.x * blockDim.x) {
        int kc = i >> 18, n = (i >> 9) & 511, k = i & 511;
        g_cwb[i] = __float2bfloat16(conv_w[n * 2048 + k * 4 + kc]);
    }
}

// ---------------- LayerNorm -> bf16 ----------------
__global__ void __launch_bounds__(256) ln_kernel(const float* __restrict__ x,
                                                 const float* __restrict__ lw,
                                                 const float* __restrict__ lb) {
    __shared__ float red[256];
    int row = blockIdx.x, t = threadIdx.x;
    float v = x[row * 256 + t];
    red[t] = v; __syncthreads();
    for (int s = 128; s > 0; s >>= 1) { if (t < s) red[t] += red[t + s]; __syncthreads(); }
    float mu = red[0] * (1.0f / 256.0f); __syncthreads();
    float dv = v - mu;
    red[t] = dv * dv; __syncthreads();
    for (int s = 128; s > 0; s >>= 1) { if (t < s) red[t] += red[t + s]; __syncthreads(); }
    float var = red[0] * (1.0f / 256.0f);
    g_xnb[row * 256 + t] = __float2bfloat16(dv * rsqrtf(var + 1e-5f) * lw[t] + lb[t]);
}

// ---------------- MMA GEMM common ids ----------------
#define GEMM_IDS                                                                 \
    int tid = threadIdx.x, lane = tid & 31, wid = tid >> 5;                      \
    int wr = wid >> 1, wc = wid & 1;                                             \
    int srow = tid >> 1, shalf = tid & 1;                                        \
    int ar = wr * 32 + (lane & 15), ac = (lane >> 4) * 8;                        \
    int brw = wc * 32 + (lane & 7) + ((lane >> 4) * 8), bc = ((lane >> 3) & 1) * 8;

#define GEMM_MMA_STEP()                                                          \
    do {                                                                         \
        uint32_t afr[2][4], bfr[2][4];                                           \
        ldsm_x4(afr[0], smem_u32(&As[ar][ac]));                                  \
        ldsm_x4(afr[1], smem_u32(&As[ar + 16][ac]));                             \
        ldsm_x4(bfr[0], smem_u32(&Ws[brw][bc]));                                 \
        ldsm_x4(bfr[1], smem_u32(&Ws[brw + 16][bc]));                            \
        _Pragma("unroll")                                                        \
        for (int mt = 0; mt < 2; ++mt) {                                         \
            mma_bf16(cfr[mt][0], afr[mt], bfr[0] + 0);                           \
            mma_bf16(cfr[mt][1], afr[mt], bfr[0] + 2);                           \
            mma_bf16(cfr[mt][2], afr[mt], bfr[1] + 0);                           \
            mma_bf16(cfr[mt][3], afr[mt], bfr[1] + 2);                           \
        }                                                                        \
    } while (0)

// xz = xn @ W_in^T ; split xp(bf16) / silu(z)(fp32)
__global__ void __launch_bounds__(128) gemm_xz() {
    __shared__ __align__(16) __nv_bfloat16 As[64][16];
    __shared__ __align__(16) __nv_bfloat16 Ws[64][16];
    int m0 = blockIdx.y * 64, n0 = blockIdx.x * 64;
    GEMM_IDS
    float cfr[2][4][4] = {};
    uint4 pa = *(const uint4*)&g_xnb[(m0 + srow) * 256 + shalf * 8];
    uint4 pw = *(const uint4*)&g_Winb[(n0 + srow) * 256 + shalf * 8];
    for (int k0 = 0; k0 < 256; k0 += 16) {
        __syncthreads();
        *(uint4*)&As[srow][shalf * 8] = pa;
        *(uint4*)&Ws[srow][shalf * 8] = pw;
        __syncthreads();
        if (k0 + 16 < 256) {
            pa = *(const uint4*)&g_xnb[(m0 + srow) * 256 + k0 + 16 + shalf * 8];
            pw = *(const uint4*)&g_Winb[(n0 + srow) * 256 + k0 + 16 + shalf * 8];
        }
        GEMM_MMA_STEP();
    }
    int gr = lane >> 2, tc2 = (lane & 3) * 2;
#pragma unroll
    for (int mt = 0; mt < 2; ++mt)
#pragma unroll
        for (int nt = 0; nt < 4; ++nt)
#pragma unroll
            for (int e = 0; e < 4; ++e) {
                int m = m0 + wr * 32 + mt * 16 + gr + ((e >> 1) * 8);
                int n = n0 + wc * 32 + nt * 8 + tc2 + (e & 1);
                float v = cfr[mt][nt][e];
                if (n < 512) g_xpb[m * 512 + n] = __float2bfloat16(v);
                else         g_sz[m * 512 + (n - 512)] = v / (1.0f + __expf(-v));
            }
}

// xact = silu(conv(xp)+b): 4 shifted GEMM passes, flattened K loop
__global__ void __launch_bounds__(128) gemm_conv(const float* __restrict__ conv_b) {
    __shared__ __align__(16) __nv_bfloat16 As[64][16];
    __shared__ __align__(16) __nv_bfloat16 Ws[64][16];
    int m0 = blockIdx.y * 64, n0 = blockIdx.x * 64;
    GEMM_IDS
    float cfr[2][4][4] = {};
    auto ldA = [&](int kk) -> uint4 {
        int kc = kk >> 5, k0 = (kk & 31) << 4;
        int tsrc = ((m0 + srow) & 511) - 3 + kc;
        uint4 v = make_uint4(0u, 0u, 0u, 0u);
        if (tsrc >= 0)
            v = *(const uint4*)&g_xpb[(long long)(m0 + srow - 3 + kc) * 512 + k0 + shalf * 8];
        return v;
    };
    auto ldW = [&](int kk) -> uint4 {
        int kc = kk >> 5, k0 = (kk & 31) << 4;
        return *(const uint4*)&g_cwb[kc * 262144 + (n0 + srow) * 512 + k0 + shalf * 8];
    };
    uint4 pa = ldA(0), pw = ldW(0);
    for (int kk = 0; kk < 128; ++kk) {
        __syncthreads();
        *(uint4*)&As[srow][shalf * 8] = pa;
        *(uint4*)&Ws[srow][shalf * 8] = pw;
        __syncthreads();
        if (kk + 1 < 128) { pa = ldA(kk + 1); pw = ldW(kk + 1); }
        GEMM_MMA_STEP();
    }
    int gr = lane >> 2, tc2 = (lane & 3) * 2;
#pragma unroll
    for (int mt = 0; mt < 2; ++mt)
#pragma unroll
        for (int nt = 0; nt < 4; ++nt)
#pragma unroll
            for (int e = 0; e < 4; ++e) {
                int m = m0 + wr * 32 + mt * 16 + gr + ((e >> 1) * 8);
                int n = n0 + wc * 32 + nt * 8 + tc2 + (e & 1);
                float v = cfr[mt][nt][e] + conv_b[n];
                g_xact[m * 512 + n] = v / (1.0f + __expf(-v));
            }
}

// out = P @ W_out^T + x
__global__ void __launch_bounds__(128) gemm_out(const float* __restrict__ x,
                                                float* __restrict__ out) {
    __shared__ __align__(16) __nv_bfloat16 As[64][16];
    __shared__ __align__(16) __nv_bfloat16 Ws[64][16];
    int m0 = blockIdx.y * 64, n0 = blockIdx.x * 64;
    GEMM_IDS
    float cfr[2][4][4] = {};
    uint4 pa = *(const uint4*)&g_Pb[(m0 + srow) * 512 + shalf * 8];
    uint4 pw = *(const uint4*)&g_Woutb[(n0 + srow) * 512 + shalf * 8];
    for (int k0 = 0; k0 < 512; k0 += 16) {
        __syncthreads();
        *(uint4*)&As[srow][shalf * 8] = pa;
        *(uint4*)&Ws[srow][shalf * 8] = pw;
        __syncthreads();
        if (k0 + 16 < 512) {
            pa = *(const uint4*)&g_Pb[(m0 + srow) * 512 + k0 + 16 + shalf * 8];
            pw = *(const uint4*)&g_Woutb[(n0 + srow) * 512 + k0 + 16 + shalf * 8];
        }
        GEMM_MMA_STEP();
    }
    int gr = lane >> 2, tc2 = (lane & 3) * 2;
#pragma unroll
    for (int mt = 0; mt < 2; ++mt)
#pragma unroll
        for (int nt = 0; nt < 4; ++nt)
#pragma unroll
            for (int e = 0; e < 4; ++e) {
                int m = m0 + wr * 32 + mt * 16 + gr + ((e >> 1) * 8);
                int n = n0 + wc * 32 + nt * 8 + tc2 + (e & 1);
                out[m * 256 + n] = cfr[mt][nt][e] + x[m * 256 + n];
            }
}

// ---------------- ssm ----------------
__global__ void __launch_bounds__(128) ssm_kernel(const float* __restrict__ W_xp,
                                                  const float* __restrict__ W_dt,
                                                  const float* __restrict__ b_dt) {
    __shared__ float xs[512];
    __shared__ float ssm_sh[33];
    int row = blockIdx.x, tid = threadIdx.x, lane = tid & 31, wid = tid >> 5;
    for (int i = tid; i < 512; i += 128) xs[i] = g_xact[row * 512 + i];
    __syncthreads();
    for (int o = wid; o < 33; o += 4) {
        float p = 0.f;
        for (int i = lane; i < 512; i += 32) p += xs[i] * W_xp[o * 512 + i];
        for (int k = 16; k > 0; k >>= 1) p += __shfl_xor_sync(0xffffffffu, p, k);
        if (lane == 0) ssm_sh[o] = p;
    }
    __syncthreads();
    if (tid < 16) {
        g_Bmb[row * 16 + tid] = __float2bfloat16(ssm_sh[1 + tid]);
        g_Cmb[row * 16 + tid] = __float2bfloat16(ssm_sh[17 + tid]);
    }
    float s0 = ssm_sh[0];
    for (int d = tid; d < 512; d += 128) {
        float v = s0 * W_dt[d] + b_dt[d];
        g_decay[row * 512 + d] = 1.0f / (1.0f + expf(v));  // exp(-softplus(v))
    }
}

// ---------------- deg / cond ----------------
__global__ void __launch_bounds__(256) deg_kernel(const float* __restrict__ adj) {
    __shared__ float rs[256];
    __shared__ int   ra[256];
    int row = blockIdx.x, b = row >> 9, t = row & 511;
    const float* a = adj + (size_t)(b * 512 + t) * 512;
    float s = 0.f; int any = 0;
    for (int i = threadIdx.x; i < t; i += 256) { float v = a[i]; s += v; any |= (v > 0.f); }
    rs[threadIdx.x] = s; ra[threadIdx.x] = any; __syncthreads();
    for (int k = 128; k > 0; k >>= 1) {
        if (threadIdx.x < k) { rs[threadIdx.x] += rs[threadIdx.x + k]; ra[threadIdx.x] |= ra[threadIdx.x + k]; }
        __syncthreads();
    }
    if (threadIdx.x == 0) {
        g_invdeg[row] = 1.0f / fmaxf(rs[0], 1.0f);
        g_any[row] = ra[0] ? 1.f : 0.f;
    }
}
__global__ void cond_kernel() {
    int t = blockIdx.x * blockDim.x + threadIdx.x;
    if (t < 512) g_condT[t] = (t > 0 && (g_any[t] > 0.f || g_any[512 + t] > 0.f)) ? 1.f : 0.f;
}

// ---------------- scan: per-(b,d); pipelined MMA Gpre + register-G sequential ----------------
__global__ void __launch_bounds__(128) scan_kernel(const float* __restrict__ Wr,
                                                   const float* __restrict__ br) {
    __shared__ __align__(16) __nv_bfloat16 hist[512][16];       // 16384
    __shared__ __align__(16) float Gsh[32][16];                 // 2048
    __shared__ __align__(16) unsigned char ubuf[4][2048];       // slots 0-2: warp tile / GP partial, slot 3: phase-A tile
    __shared__ __align__(16) __nv_bfloat16 adjC[32][32];        // 2048
    __shared__ __align__(16) __nv_bfloat16 Bs[32][16];          // 1024
    __shared__ float dec_s[32], xa_s[32], ivd_s[32], cond_s[32];

#define ADJS(w_) ((__nv_bfloat16(*)[32])ubuf[w_])
#define GPf(w_)  ((float(*)[16])ubuf[w_])

    int tid = threadIdx.x, lane = tid & 31, wid = tid >> 5;
    int seq = blockIdx.x, b = seq >> 9, d = seq & 511;
    const long long badj = (long long)b * 512 * 512;

    // warp0 private constants
    float Wr_r[16], br_r = 0.f, Greg[16], hreg = 0.f;
    int n = lane & 15;
    if (wid == 0) {
#pragma unroll
        for (int m = 0; m < 16; ++m) Wr_r[m] = Wr[n * 16 + m];
        br_r = br[n];
    }

    for (int c = 0; c < 16; ++c) {
        int c0 = c << 5;

        // ================= PHASE A =================
        if (wid == 1) {
            if (c == 0) {
                for (int e = lane; e < 512; e += 32) Gsh[e >> 4][e & 15] = 0.f;
            } else {
                // finish Gpre[c]: GP sums + last tile (rows chunk c, cols chunk c-1) x hist[c-1]
                float cfr2[2][2][4] = {};
                int sb = (c - 1) << 5;
                uint32_t afr[4], bfr[4];
#pragma unroll
                for (int kt = 0; kt < 2; ++kt) {
                    ldsm_x4t(bfr, smem_u32(&hist[sb + kt * 16 + (lane & 15)][(lane >> 4) * 8]));
#pragma unroll
                    for (int mt = 0; mt < 2; ++mt) {
                        ldsm_x4(afr, smem_u32(&ADJS(3)[mt * 16 + (lane & 15)][kt * 16 + (lane >> 4) * 8]));
                        mma_bf16(cfr2[mt][0], afr, bfr + 0);
                        mma_bf16(cfr2[mt][1], afr, bfr + 2);
                    }
                }
                int gr = lane >> 2, tc2 = (lane & 3) * 2;
#pragma unroll
                for (int mt = 0; mt < 2; ++mt)
#pragma unroll
                    for (int nt = 0; nt < 2; ++nt)
#pragma unroll
                        for (int e = 0; e < 4; ++e) {
                            int r = mt * 16 + gr + (e >> 1) * 8;
                            int col = nt * 8 + tc2 + (e & 1);
                            Gsh[r][col] = GPf(0)[r][col] + GPf(1)[r][col] + GPf(2)[r][col]
                                          + cfr2[mt][nt][e];
                        }
            }
        } else if (wid >= 2) {
            // stage chunk c arrays
            int i = tid - 64;  // 0..63
            if (i < 32) {
                int row = b * 512 + c0 + i;
                dec_s[i]  = g_decay[(long long)row * 512 + d];
                xa_s[i]   = g_xact [(long long)row * 512 + d];
                ivd_s[i]  = g_invdeg[row];
                cond_s[i] = g_condT[c0 + i];
            }
            {
                int r = i >> 1, hh = i & 1;
                *(uint4*)&Bs[r][hh * 8] = *(const uint4*)&g_Bmb[(b * 512 + c0 + r) * 16 + hh * 8];
            }
#pragma unroll
            for (int k = 0; k < 2; ++k) {
                int e = i + 64 * k, tt = e >> 2, q = e & 3;
                *(uint4*)&adjC[tt][q * 8] =
                    *(const uint4*)&g_adjb[badj + (long long)(c0 + tt) * 512 + c0 + q * 8];
            }
        }
        __syncthreads();

        // ================= PHASE B =================
        if (wid == 0) {
            // load Gpre into registers: lanes 0-15 rows 0-15, lanes 16-31 rows 16-31
            int rbase = (lane < 16) ? 0 : 16;
#pragma unroll
            for (int q = 0; q < 16; ++q) Greg[q] = Gsh[rbase + q][n];
            bool hi = lane >= 16;
            // 32 sequential steps, fully unrolled
#pragma unroll
            for (int j = 0; j < 32; ++j) {
                float ivd = ivd_s[j];
                float gsrc = Greg[j & 15] * ivd;  // valid in the half owning row j
                float accb = br_r;
#pragma unroll
                for (int m = 0; m < 16; ++m) {
                    int src = (j < 16) ? m : 16 + m;
                    accb += Wr_r[m] * __shfl_sync(0xffffffffu, gsrc, src);
                }
                float bo = 0.1f * accb / (1.0f + __expf(-accb));
                float h = hreg * dec_s[j] + xa_s[j] * __bfloat162float(Bs[j][n])
                          + cond_s[j] * bo;
                hreg = h;
                if (!hi) hist[c0 + j][n] = __float2bfloat16(h);
                // scatter into future rows of own half
#pragma unroll
                for (int q = 0; q < 16; ++q) {
                    int t = (hi ? 16 : 0) + q;
                    if (t > j) Greg[q] += __bfloat162float(adjC[t][j]) * h;
                }
            }
        } else {
            int w = wid - 1;
            float cfr[2][2][4] = {};
            if (c < 15) {
                int r1 = (c + 1) << 5;
                for (int st = w; st < c; st += 3) {
#pragma unroll
                    for (int k = 0; k < 4; ++k) {
                        int e = lane + 32 * k, tt = e >> 2, q = e & 3;
                        *(uint4*)&ADJS(w)[tt][q * 8] =
                            *(const uint4*)&g_adjb[badj + (long long)(r1 + tt) * 512 + st * 32 + q * 8];
                    }
                    __syncwarp();
                    int sb = st << 5;
                    uint32_t afr[4], bfr[4];
#pragma unroll
                    for (int kt = 0; kt < 2; ++kt) {
                        ldsm_x4t(bfr, smem_u32(&hist[sb + kt * 16 + (lane & 15)][(lane >> 4) * 8]));
#pragma unroll
                        for (int mt = 0; mt < 2; ++mt) {
                            ldsm_x4(afr, smem_u32(&ADJS(w)[mt * 16 + (lane & 15)][kt * 16 + (lane >> 4) * 8]));
                            mma_bf16(cfr[mt][0], afr, bfr + 0);
                            mma_bf16(cfr[mt][1], afr, bfr + 2);
                        }
                    }
                    __syncwarp();
                }
            }
            // deposit partial into own slot (float alias)
            {
                int gr = lane >> 2, tc2 = (lane & 3) * 2;
#pragma unroll
                for (int mt = 0; mt < 2; ++mt)
#pragma unroll
                    for (int nt = 0; nt < 2; ++nt)
#pragma unroll
                        for (int e = 0; e < 4; ++e) {
                            int r = mt * 16 + gr + (e >> 1) * 8;
                            int col = nt * 8 + tc2 + (e & 1);
                            GPf(w)[r][col] = cfr[mt][nt][e];
                        }
            }
            if (wid == 1 && c < 15) {  // prefetch phase-A tile for c+1: rows chunk c+1, cols chunk c
                int r1 = (c + 1) << 5;
#pragma unroll
                for (int k = 0; k < 4; ++k) {
                    int e = lane + 32 * k, tt = e >> 2, q = e & 3;
                    *(uint4*)&ADJS(3)[tt][q * 8] =
                        *(const uint4*)&g_adjb[badj + (long long)(r1 + tt) * 512 + c0 + q * 8];
                }
            }
            if (wid == 3 && c > 0) {  // deferred y/P for chunk c-1
                int cp0 = (c - 1) << 5;
                int rowg = b * 512 + cp0 + lane;
                float y = 0.f;
#pragma unroll
                for (int n2 = 0; n2 < 16; ++n2)
                    y += __bfloat162float(hist[cp0 + lane][n2]) *
                         __bfloat162float(g_Cmb[rowg * 16 + n2]);
                g_Pb[(long long)rowg * 512 + d] =
                    __float2bfloat16(y * g_sz[(long long)rowg * 512 + d]);
            }
        }
        __syncthreads();
    }

    // epilogue: y/P for chunk 15
    if (tid < 32) {
        int cp0 = 15 << 5;
        int rowg = b * 512 + cp0 + tid;
        float y = 0.f;
#pragma unroll
        for (int n2 = 0; n2 < 16; ++n2)
            y += __bfloat162float(hist[cp0 + tid][n2]) *
                 __bfloat162float(g_Cmb[rowg * 16 + n2]);
        g_Pb[(long long)rowg * 512 + d] =
            __float2bfloat16(y * g_sz[(long long)rowg * 512 + d]);
    }
#undef ADJS
#undef GPf
}

// ---------------- launch ----------------
extern "C" void kernel_launch(void* const* d_in, const int* in_sizes, int n_in,
                              void* d_out, int out_size) {
    const float* x      = (const float*)d_in[0];
    const float* adj    = (const float*)d_in[1];
    const float* ln_w   = (const float*)d_in[2];
    const float* ln_b   = (const float*)d_in[3];
    const float* W_in   = (const float*)d_in[4];
    const float* conv_w = (const float*)d_in[5];
    const float* conv_b = (const float*)d_in[6];
    const float* W_xp   = (const float*)d_in[7];
    const float* W_dt   = (const float*)d_in[8];
    const float* b_dt   = (const float*)d_in[9];
    const float* Wr     = (const float*)d_in[10];
    const float* br     = (const float*)d_in[11];
    const float* W_out  = (const float*)d_in[12];
    float* out = (float*)d_out;

    cvt_misc<<<1024, 256>>>(W_in, W_out, adj);
    cvt_convw<<<1024, 256>>>(conv_w);
    ln_kernel<<<1024, 256>>>(x, ln_w, ln_b);
    gemm_xz<<<dim3(16, 16), 128>>>();
    deg_kernel<<<1024, 256>>>(adj);
    cond_kernel<<<2, 256>>>();
    gemm_conv<<<dim3(8, 16), 128>>>(conv_b);
    ssm_kernel<<<1024, 128>>>(W_xp, W_dt, b_dt);
    scan_kernel<<<1024, 128>>>(Wr, br);
    gemm_out<<<dim3(4, 16), 128>>>(x, out);
}

// round 5
// speedup vs baseline: 3.1302x; 1.3737x over previous
#include <cuda_runtime.h>
#include <cuda_bf16.h>
#include <cstdint>

// B=2, S=512, D=256, N=16, DC=4, DI=512, CHUNK=32, rows=1024

// ---------------- scratch ----------------
__device__ __nv_bfloat16 g_xpb [1024*512];
__device__ float         g_sz  [1024*512];
__device__ float         g_xact[1024*512];
__device__ float         g_decay[1024*512];
__device__ __nv_bfloat16 g_Bmb [1024*16];
__device__ __nv_bfloat16 g_Cmb [1024*16];
__device__ float         g_invdeg[1024];
__device__ float         g_any [1024];
__device__ __nv_bfloat16 g_Pb  [1024*512];
__device__ __nv_bfloat16 g_Woutb[256*512];
__device__ __nv_bfloat16 g_adjb [2*512*512];
__device__ __nv_bfloat16 g_cwb  [4*512*512];   // [kc][n][k]

// ---------------- mma helpers ----------------
__device__ __forceinline__ uint32_t smem_u32(const void* p) {
    return (uint32_t)__cvta_generic_to_shared(p);
}
__device__ __forceinline__ void ldsm_x4(uint32_t* r, uint32_t a) {
    asm volatile("ldmatrix.sync.aligned.m8n8.x4.shared.b16 {%0,%1,%2,%3}, [%4];\n"
                 : "=r"(r[0]), "=r"(r[1]), "=r"(r[2]), "=r"(r[3]) : "r"(a));
}
__device__ __forceinline__ void ldsm_x4t(uint32_t* r, uint32_t a) {
    asm volatile("ldmatrix.sync.aligned.m8n8.x4.trans.shared.b16 {%0,%1,%2,%3}, [%4];\n"
                 : "=r"(r[0]), "=r"(r[1]), "=r"(r[2]), "=r"(r[3]) : "r"(a));
}
__device__ __forceinline__ void mma_bf16(float* c, const uint32_t* a, const uint32_t* b) {
    asm volatile(
        "mma.sync.aligned.m16n8k16.row.col.f32.bf16.bf16.f32 "
        "{%0,%1,%2,%3}, {%4,%5,%6,%7}, {%8,%9}, {%0,%1,%2,%3};\n"
        : "+f"(c[0]), "+f"(c[1]), "+f"(c[2]), "+f"(c[3])
        : "r"(a[0]), "r"(a[1]), "r"(a[2]), "r"(a[3]), "r"(b[0]), "r"(b[1]));
}
__device__ __forceinline__ uint4 pack8(float4 a, float4 b) {
    __nv_bfloat162 r0 = __floats2bfloat162_rn(a.x, a.y);
    __nv_bfloat162 r1 = __floats2bfloat162_rn(a.z, a.w);
    __nv_bfloat162 r2 = __floats2bfloat162_rn(b.x, b.y);
    __nv_bfloat162 r3 = __floats2bfloat162_rn(b.z, b.w);
    uint4 u;
    u.x = *(uint32_t*)&r0; u.y = *(uint32_t*)&r1;
    u.z = *(uint32_t*)&r2; u.w = *(uint32_t*)&r3;
    return u;
}

// ---------------- GEMM ids / mma step ----------------
#define GEMM_IDS                                                                 \
    int tid = threadIdx.x, lane = tid & 31, wid = tid >> 5;                      \
    int wr = wid >> 1, wc = wid & 1;                                             \
    int srow = tid >> 1, shalf = tid & 1;                                        \
    int ar = wr * 32 + (lane & 15), ac = (lane >> 4) * 8;                        \
    int brw = wc * 32 + (lane & 7) + ((lane >> 4) * 8), bc = ((lane >> 3) & 1) * 8;

// ---------------- launch 1: LN + xz GEMM + weight/adj conversions ----------------
// xz = LN(x) @ W_in^T ; split xp(bf16) / silu(z)(fp32). A tile held entirely in smem.
__global__ void __launch_bounds__(128) gemm_xz(const float* __restrict__ x,
                                               const float* __restrict__ lnw,
                                               const float* __restrict__ lnb,
                                               const float* __restrict__ W_in,
                                               const float* __restrict__ conv_w,
                                               const float* __restrict__ adj,
                                               const float* __restrict__ W_out) {
    __shared__ __align__(16) __nv_bfloat16 Xs[64][264];   // padded: stride 528B, conflict-free ldsm
    __shared__ __align__(16) __nv_bfloat16 Ws[2][64][16];
    int m0 = blockIdx.y * 64, n0 = blockIdx.x * 64;
    GEMM_IDS
    (void)brw; (void)bc;

    // --- LN: 2 threads per row ---
    {
        int r = tid >> 1, hf = tid & 1;
        const float4* xr = (const float4*)(x + (size_t)(m0 + r) * 256 + hf * 128);
        float s = 0.f, s2 = 0.f;
#pragma unroll 8
        for (int i = 0; i < 32; ++i) {
            float4 v = xr[i];
            s += v.x + v.y + v.z + v.w;
            s2 += v.x * v.x + v.y * v.y + v.z * v.z + v.w * v.w;
        }
        s  += __shfl_xor_sync(0xffffffffu, s, 1);
        s2 += __shfl_xor_sync(0xffffffffu, s2, 1);
        float mu = s * (1.f / 256.f);
        float var = s2 * (1.f / 256.f) - mu * mu;
        float rstd = rsqrtf(var + 1e-5f);
#pragma unroll 8
        for (int i = 0; i < 32; ++i) {
            float4 v = xr[i];
            int col = hf * 128 + i * 4;
            float4 w = *(const float4*)(lnw + col);
            float4 bb = *(const float4*)(lnb + col);
            Xs[r][col + 0] = __float2bfloat16((v.x - mu) * rstd * w.x + bb.x);
            Xs[r][col + 1] = __float2bfloat16((v.y - mu) * rstd * w.y + bb.y);
            Xs[r][col + 2] = __float2bfloat16((v.z - mu) * rstd * w.z + bb.z);
            Xs[r][col + 3] = __float2bfloat16((v.w - mu) * rstd * w.w + bb.w);
        }
    }

    float cfr[2][4][4] = {};
    auto ldW = [&](int k0) -> uint4 {
        const float* p = W_in + (size_t)(n0 + srow) * 256 + k0 + shalf * 8;
        return pack8(*(const float4*)p, *(const float4*)(p + 4));
    };
    uint4 pw = ldW(0);
    *(uint4*)&Ws[0][srow][shalf * 8] = pw;
    __syncthreads();
    int pb = 0;
    for (int k0 = 0; k0 < 256; k0 += 16, pb ^= 1) {
        if (k0 + 16 < 256) {
            pw = ldW(k0 + 16);
            *(uint4*)&Ws[pb ^ 1][srow][shalf * 8] = pw;
        }
        uint32_t afr[2][4], bfr[2][4];
        ldsm_x4(afr[0], smem_u32(&Xs[ar][k0 + ac]));
        ldsm_x4(afr[1], smem_u32(&Xs[ar + 16][k0 + ac]));
        {
            int brw2 = wc * 32 + (lane & 7) + ((lane >> 4) * 8), bc2 = ((lane >> 3) & 1) * 8;
            ldsm_x4(bfr[0], smem_u32(&Ws[pb][brw2][bc2]));
            ldsm_x4(bfr[1], smem_u32(&Ws[pb][brw2 + 16][bc2]));
        }
#pragma unroll
        for (int mt = 0; mt < 2; ++mt) {
            mma_bf16(cfr[mt][0], afr[mt], bfr[0] + 0);
            mma_bf16(cfr[mt][1], afr[mt], bfr[0] + 2);
            mma_bf16(cfr[mt][2], afr[mt], bfr[1] + 0);
            mma_bf16(cfr[mt][3], afr[mt], bfr[1] + 2);
        }
        __syncthreads();
    }
    int gr = lane >> 2, tc2 = (lane & 3) * 2;
#pragma unroll
    for (int mt = 0; mt < 2; ++mt)
#pragma unroll
        for (int nt = 0; nt < 4; ++nt)
#pragma unroll
            for (int e = 0; e < 4; ++e) {
                int m = m0 + wr * 32 + mt * 16 + gr + ((e >> 1) * 8);
                int n = n0 + wc * 32 + nt * 8 + tc2 + (e & 1);
                float v = cfr[mt][nt][e];
                if (n < 512) g_xpb[m * 512 + n] = __float2bfloat16(v);
                else         g_sz[m * 512 + (n - 512)] = v / (1.0f + __expf(-v));
            }

    // --- side jobs: convert conv_w / adj / W_out to bf16 (grid-stride) ---
    int gtid = (blockIdx.y * gridDim.x + blockIdx.x) * 128 + tid;
    const int GT = 16 * 16 * 128;
    for (int i = gtid; i < 4 * 512 * 512; i += GT) {
        int kc = i >> 18, nn = (i >> 9) & 511, kk = i & 511;
        g_cwb[i] = __float2bfloat16(conv_w[nn * 2048 + kk * 4 + kc]);
    }
    for (int i = gtid; i < 2 * 512 * 512; i += GT)
        g_adjb[i] = __float2bfloat16(adj[i]);
    for (int i = gtid; i < 256 * 512; i += GT)
        g_Woutb[i] = __float2bfloat16(W_out[i]);
}

// ---------------- launch 2: conv GEMM ----------------
__global__ void __launch_bounds__(128) gemm_conv(const float* __restrict__ conv_b) {
    __shared__ __align__(16) __nv_bfloat16 As[64][16];
    __shared__ __align__(16) __nv_bfloat16 Ws[64][16];
    int m0 = blockIdx.y * 64, n0 = blockIdx.x * 64;
    GEMM_IDS
    float cfr[2][4][4] = {};
    auto ldA = [&](int kk) -> uint4 {
        int kc = kk >> 5, k0 = (kk & 31) << 4;
        int tsrc = ((m0 + srow) & 511) - 3 + kc;
        uint4 v = make_uint4(0u, 0u, 0u, 0u);
        if (tsrc >= 0)
            v = *(const uint4*)&g_xpb[(long long)(m0 + srow - 3 + kc) * 512 + k0 + shalf * 8];
        return v;
    };
    auto ldWc = [&](int kk) -> uint4 {
        int kc = kk >> 5, k0 = (kk & 31) << 4;
        return *(const uint4*)&g_cwb[kc * 262144 + (n0 + srow) * 512 + k0 + shalf * 8];
    };
    uint4 pa = ldA(0), pw = ldWc(0);
    for (int kk = 0; kk < 128; ++kk) {
        __syncthreads();
        *(uint4*)&As[srow][shalf * 8] = pa;
        *(uint4*)&Ws[srow][shalf * 8] = pw;
        __syncthreads();
        if (kk + 1 < 128) { pa = ldA(kk + 1); pw = ldWc(kk + 1); }
        uint32_t afr[2][4], bfr[2][4];
        ldsm_x4(afr[0], smem_u32(&As[ar][ac]));
        ldsm_x4(afr[1], smem_u32(&As[ar + 16][ac]));
        ldsm_x4(bfr[0], smem_u32(&Ws[brw][bc]));
        ldsm_x4(bfr[1], smem_u32(&Ws[brw + 16][bc]));
#pragma unroll
        for (int mt = 0; mt < 2; ++mt) {
            mma_bf16(cfr[mt][0], afr[mt], bfr[0] + 0);
            mma_bf16(cfr[mt][1], afr[mt], bfr[0] + 2);
            mma_bf16(cfr[mt][2], afr[mt], bfr[1] + 0);
            mma_bf16(cfr[mt][3], afr[mt], bfr[1] + 2);
        }
    }
    int gr = lane >> 2, tc2 = (lane & 3) * 2;
#pragma unroll
    for (int mt = 0; mt < 2; ++mt)
#pragma unroll
        for (int nt = 0; nt < 4; ++nt)
#pragma unroll
            for (int e = 0; e < 4; ++e) {
                int m = m0 + wr * 32 + mt * 16 + gr + ((e >> 1) * 8);
                int n = n0 + wc * 32 + nt * 8 + tc2 + (e & 1);
                float v = cfr[mt][nt][e] + conv_b[n];
                g_xact[m * 512 + n] = v / (1.0f + __expf(-v));
            }
}

// ---------------- launch 3: ssm + deg ----------------
__global__ void __launch_bounds__(128) ssm_deg(const float* __restrict__ W_xp,
                                               const float* __restrict__ W_dt,
                                               const float* __restrict__ b_dt,
                                               const float* __restrict__ adj) {
    __shared__ float xs[512];
    __shared__ float ssm_sh[33];
    __shared__ float rs[4];
    __shared__ int   ra[4];
    int row = blockIdx.x, tid = threadIdx.x, lane = tid & 31, wid = tid >> 5;
    int b = row >> 9, t = row & 511;

    for (int i = tid; i < 512; i += 128) xs[i] = g_xact[row * 512 + i];

    // deg reduction on adj row
    {
        const float* a = adj + (size_t)row * 512;
        float s = 0.f; int any = 0;
        for (int i = tid; i < t; i += 128) { float v = a[i]; s += v; any |= (v > 0.f); }
        for (int k = 16; k > 0; k >>= 1) {
            s += __shfl_xor_sync(0xffffffffu, s, k);
            any |= __shfl_xor_sync(0xffffffffu, any, k);
        }
        if (lane == 0) { rs[wid] = s; ra[wid] = any; }
    }
    __syncthreads();
    if (tid == 0) {
        float s = rs[0] + rs[1] + rs[2] + rs[3];
        int any = ra[0] | ra[1] | ra[2] | ra[3];
        g_invdeg[row] = 1.0f / fmaxf(s, 1.0f);
        g_any[row] = any ? 1.f : 0.f;
    }
    for (int o = wid; o < 33; o += 4) {
        float p = 0.f;
        for (int i = lane; i < 512; i += 32) p += xs[i] * W_xp[o * 512 + i];
        for (int k = 16; k > 0; k >>= 1) p += __shfl_xor_sync(0xffffffffu, p, k);
        if (lane == 0) ssm_sh[o] = p;
    }
    __syncthreads();
    if (tid < 16) {
        g_Bmb[row * 16 + tid] = __float2bfloat16(ssm_sh[1 + tid]);
        g_Cmb[row * 16 + tid] = __float2bfloat16(ssm_sh[17 + tid]);
    }
    float s0 = ssm_sh[0];
    for (int d = tid; d < 512; d += 128) {
        float v = s0 * W_dt[d] + b_dt[d];
        g_decay[row * 512 + d] = 1.0f / (1.0f + expf(v));  // exp(-softplus(v))
    }
}

// ---------------- launch 4: scan ----------------
__global__ void __launch_bounds__(128, 7) scan_kernel(const float* __restrict__ Wr,
                                                      const float* __restrict__ br) {
    __shared__ __align__(16) __nv_bfloat16 hist[512][16];       // 16384
    __shared__ __align__(16) float Gsh[32][16];                 // 2048
    __shared__ __align__(16) unsigned char ubuf[4][2048];       // 8192
    __shared__ __align__(16) __nv_bfloat16 adjC[32][32];        // 2048
    __shared__ __align__(16) float xB_s[32][16];                // 2048
    __shared__ float dec_s[32], ivd_s[32], cond_s[32];

#define ADJS(w_) ((__nv_bfloat16(*)[32])ubuf[w_])
#define GPf(w_)  ((float(*)[16])ubuf[w_])

    int tid = threadIdx.x, lane = tid & 31, wid = tid >> 5;
    int seq = blockIdx.x, b = seq >> 9, d = seq & 511;
    const long long badj = (long long)b * 512 * 512;

    float Wr_r[16], br_r = 0.f, Greg[16], hreg = 0.f;
    int n = lane & 15;
    if (wid == 0) {
#pragma unroll
        for (int m = 0; m < 16; ++m) Wr_r[m] = Wr[n * 16 + m];
        br_r = br[n];
    }

    for (int c = 0; c < 16; ++c) {
        int c0 = c << 5;

        // ================= PHASE A =================
        if (wid == 1) {
            if (c == 0) {
                for (int e = lane; e < 512; e += 32) Gsh[e >> 4][e & 15] = 0.f;
            } else {
                float cfr2[2][2][4] = {};
                int sb = (c - 1) << 5;
                uint32_t afr[4], bfr[4];
#pragma unroll
                for (int kt = 0; kt < 2; ++kt) {
                    ldsm_x4t(bfr, smem_u32(&hist[sb + kt * 16 + (lane & 15)][(lane >> 4) * 8]));
#pragma unroll
                    for (int mt = 0; mt < 2; ++mt) {
                        ldsm_x4(afr, smem_u32(&ADJS(3)[mt * 16 + (lane & 15)][kt * 16 + (lane >> 4) * 8]));
                        mma_bf16(cfr2[mt][0], afr, bfr + 0);
                        mma_bf16(cfr2[mt][1], afr, bfr + 2);
                    }
                }
                int gr = lane >> 2, tc2 = (lane & 3) * 2;
#pragma unroll
                for (int mt = 0; mt < 2; ++mt)
#pragma unroll
                    for (int nt = 0; nt < 2; ++nt)
#pragma unroll
                        for (int e = 0; e < 4; ++e) {
                            int r = mt * 16 + gr + (e >> 1) * 8;
                            int col = nt * 8 + tc2 + (e & 1);
                            Gsh[r][col] = GPf(0)[r][col] + GPf(1)[r][col] + GPf(2)[r][col]
                                          + cfr2[mt][nt][e];
                        }
            }
        } else if (wid == 2) {
            // per-row scalars + xB = xa * B
            int j = lane;
            int row = b * 512 + c0 + j;
            float xa = g_xact[(size_t)row * 512 + d];
            dec_s[j] = g_decay[(size_t)row * 512 + d];
            ivd_s[j] = g_invdeg[row];
            int t = c0 + j;
            cond_s[j] = (t > 0 && (g_any[t] > 0.f || g_any[512 + t] > 0.f)) ? 1.f : 0.f;
            uint4 bm = *(const uint4*)&g_Bmb[row * 16];
            __nv_bfloat162* bp = (__nv_bfloat162*)&bm;
#pragma unroll
            for (int q = 0; q < 8; ++q) {
                float2 f = __bfloat1622float2(bp[q]);
                xB_s[j][2 * q]     = xa * f.x;
                xB_s[j][2 * q + 1] = xa * f.y;
            }
        } else if (wid == 3) {
#pragma unroll
            for (int k = 0; k < 4; ++k) {
                int e = lane + 32 * k, tt = e >> 2, q = e & 3;
                *(uint4*)&adjC[tt][q * 8] =
                    *(const uint4*)&g_adjb[badj + (long long)(c0 + tt) * 512 + c0 + q * 8];
            }
        }
        __syncthreads();

        // ================= PHASE B =================
        if (wid == 0) {
            int rbase = (lane < 16) ? 0 : 16;
#pragma unroll
            for (int q = 0; q < 16; ++q) Greg[q] = Gsh[rbase + q][n];
            bool hi = lane >= 16;
#pragma unroll
            for (int j = 0; j < 32; ++j) {
                float gsrc = Greg[j & 15] * ivd_s[j];
                int base = (j < 16) ? 0 : 16;
                float v0  = __shfl_sync(0xffffffffu, gsrc, base + 0);
                float v1  = __shfl_sync(0xffffffffu, gsrc, base + 1);
                float v2  = __shfl_sync(0xffffffffu, gsrc, base + 2);
                float v3  = __shfl_sync(0xffffffffu, gsrc, base + 3);
                float v4  = __shfl_sync(0xffffffffu, gsrc, base + 4);
                float v5  = __shfl_sync(0xffffffffu, gsrc, base + 5);
                float v6  = __shfl_sync(0xffffffffu, gsrc, base + 6);
                float v7  = __shfl_sync(0xffffffffu, gsrc, base + 7);
                float v8  = __shfl_sync(0xffffffffu, gsrc, base + 8);
                float v9  = __shfl_sync(0xffffffffu, gsrc, base + 9);
                float v10 = __shfl_sync(0xffffffffu, gsrc, base + 10);
                float v11 = __shfl_sync(0xffffffffu, gsrc, base + 11);
                float v12 = __shfl_sync(0xffffffffu, gsrc, base + 12);
                float v13 = __shfl_sync(0xffffffffu, gsrc, base + 13);
                float v14 = __shfl_sync(0xffffffffu, gsrc, base + 14);
                float v15 = __shfl_sync(0xffffffffu, gsrc, base + 15);
                // 4 parallel FMA chains
                float p0 = fmaf(Wr_r[0], v0, br_r);
                float p1 = Wr_r[1] * v1;
                float p2 = Wr_r[2] * v2;
                float p3 = Wr_r[3] * v3;
                p0 = fmaf(Wr_r[4], v4, p0);
                p1 = fmaf(Wr_r[5], v5, p1);
                p2 = fmaf(Wr_r[6], v6, p2);
                p3 = fmaf(Wr_r[7], v7, p3);
                p0 = fmaf(Wr_r[8], v8, p0);
                p1 = fmaf(Wr_r[9], v9, p1);
                p2 = fmaf(Wr_r[10], v10, p2);
                p3 = fmaf(Wr_r[11], v11, p3);
                p0 = fmaf(Wr_r[12], v12, p0);
                p1 = fmaf(Wr_r[13], v13, p1);
                p2 = fmaf(Wr_r[14], v14, p2);
                p3 = fmaf(Wr_r[15], v15, p3);
                float accb = (p0 + p1) + (p2 + p3);
                float bo = 0.1f * __fdividef(accb, 1.0f + __expf(-accb));
                float h = fmaf(hreg, dec_s[j], xB_s[j][n]);
                h = fmaf(cond_s[j], bo, h);
                hreg = h;
                if (!hi) hist[c0 + j][n] = __float2bfloat16(h);
#pragma unroll
                for (int q = 0; q < 16; ++q) {
                    int t = (hi ? 16 : 0) + q;
                    if (t > j) Greg[q] = fmaf(__bfloat162float(adjC[t][j]), h, Greg[q]);
                }
            }
        } else {
            int w = wid - 1;
            float cfr[2][2][4] = {};
            if (c < 15) {
                int r1 = (c + 1) << 5;
                for (int st = w; st < c; st += 3) {
#pragma unroll
                    for (int k = 0; k < 4; ++k) {
                        int e = lane + 32 * k, tt = e >> 2, q = e & 3;
                        *(uint4*)&ADJS(w)[tt][q * 8] =
                            *(const uint4*)&g_adjb[badj + (long long)(r1 + tt) * 512 + st * 32 + q * 8];
                    }
                    __syncwarp();
                    int sb = st << 5;
                    uint32_t afr[4], bfr[4];
#pragma unroll
                    for (int kt = 0; kt < 2; ++kt) {
                        ldsm_x4t(bfr, smem_u32(&hist[sb + kt * 16 + (lane & 15)][(lane >> 4) * 8]));
#pragma unroll
                        for (int mt = 0; mt < 2; ++mt) {
                            ldsm_x4(afr, smem_u32(&ADJS(w)[mt * 16 + (lane & 15)][kt * 16 + (lane >> 4) * 8]));
                            mma_bf16(cfr[mt][0], afr, bfr + 0);
                            mma_bf16(cfr[mt][1], afr, bfr + 2);
                        }
                    }
                    __syncwarp();
                }
            }
            {
                int gr = lane >> 2, tc2 = (lane & 3) * 2;
#pragma unroll
                for (int mt = 0; mt < 2; ++mt)
#pragma unroll
                    for (int nt = 0; nt < 2; ++nt)
#pragma unroll
                        for (int e = 0; e < 4; ++e) {
                            int r = mt * 16 + gr + (e >> 1) * 8;
                            int col = nt * 8 + tc2 + (e & 1);
                            GPf(w)[r][col] = cfr[mt][nt][e];
                        }
            }
            if (wid == 1 && c < 15) {
                int r1 = (c + 1) << 5;
#pragma unroll
                for (int k = 0; k < 4; ++k) {
                    int e = lane + 32 * k, tt = e >> 2, q = e & 3;
                    *(uint4*)&ADJS(3)[tt][q * 8] =
                        *(const uint4*)&g_adjb[badj + (long long)(r1 + tt) * 512 + c0 + q * 8];
                }
            }
            if (wid == 3 && c > 0) {
                int cp0 = (c - 1) << 5;
                int rowg = b * 512 + cp0 + lane;
                float y = 0.f;
#pragma unroll
                for (int n2 = 0; n2 < 16; ++n2)
                    y += __bfloat162float(hist[cp0 + lane][n2]) *
                         __bfloat162float(g_Cmb[rowg * 16 + n2]);
                g_Pb[(long long)rowg * 512 + d] =
                    __float2bfloat16(y * g_sz[(long long)rowg * 512 + d]);
            }
        }
        __syncthreads();
    }

    if (tid < 32) {
        int cp0 = 15 << 5;
        int rowg = b * 512 + cp0 + tid;
        float y = 0.f;
#pragma unroll
        for (int n2 = 0; n2 < 16; ++n2)
            y += __bfloat162float(hist[cp0 + tid][n2]) *
                 __bfloat162float(g_Cmb[rowg * 16 + n2]);
        g_Pb[(long long)rowg * 512 + d] =
            __float2bfloat16(y * g_sz[(long long)rowg * 512 + d]);
    }
#undef ADJS
#undef GPf
}

// ---------------- launch 5: out GEMM + residual ----------------
__global__ void __launch_bounds__(128) gemm_out(const float* __restrict__ x,
                                                float* __restrict__ out) {
    __shared__ __align__(16) __nv_bfloat16 As[64][16];
    __shared__ __align__(16) __nv_bfloat16 Ws[64][16];
    int m0 = blockIdx.y * 64, n0 = blockIdx.x * 64;
    GEMM_IDS
    float cfr[2][4][4] = {};
    uint4 pa = *(const uint4*)&g_Pb[(m0 + srow) * 512 + shalf * 8];
    uint4 pw = *(const uint4*)&g_Woutb[(n0 + srow) * 512 + shalf * 8];
    for (int k0 = 0; k0 < 512; k0 += 16) {
        __syncthreads();
        *(uint4*)&As[srow][shalf * 8] = pa;
        *(uint4*)&Ws[srow][shalf * 8] = pw;
        __syncthreads();
        if (k0 + 16 < 512) {
            pa = *(const uint4*)&g_Pb[(m0 + srow) * 512 + k0 + 16 + shalf * 8];
            pw = *(const uint4*)&g_Woutb[(n0 + srow) * 512 + k0 + 16 + shalf * 8];
        }
        uint32_t afr[2][4], bfr[2][4];
        ldsm_x4(afr[0], smem_u32(&As[ar][ac]));
        ldsm_x4(afr[1], smem_u32(&As[ar + 16][ac]));
        ldsm_x4(bfr[0], smem_u32(&Ws[brw][bc]));
        ldsm_x4(bfr[1], smem_u32(&Ws[brw + 16][bc]));
#pragma unroll
        for (int mt = 0; mt < 2; ++mt) {
            mma_bf16(cfr[mt][0], afr[mt], bfr[0] + 0);
            mma_bf16(cfr[mt][1], afr[mt], bfr[0] + 2);
            mma_bf16(cfr[mt][2], afr[mt], bfr[1] + 0);
            mma_bf16(cfr[mt][3], afr[mt], bfr[1] + 2);
        }
    }
    int gr = lane >> 2, tc2 = (lane & 3) * 2;
#pragma unroll
    for (int mt = 0; mt < 2; ++mt)
#pragma unroll
        for (int nt = 0; nt < 4; ++nt)
#pragma unroll
            for (int e = 0; e < 4; ++e) {
                int m = m0 + wr * 32 + mt * 16 + gr + ((e >> 1) * 8);
                int n = n0 + wc * 32 + nt * 8 + tc2 + (e & 1);
                out[m * 256 + n] = cfr[mt][nt][e] + x[m * 256 + n];
            }
}

// ---------------- launch ----------------
extern "C" void kernel_launch(void* const* d_in, const int* in_sizes, int n_in,
                              void* d_out, int out_size) {
    const float* x      = (const float*)d_in[0];
    const float* adj    = (const float*)d_in[1];
    const float* ln_w   = (const float*)d_in[2];
    const float* ln_b   = (const float*)d_in[3];
    const float* W_in   = (const float*)d_in[4];
    const float* conv_w = (const float*)d_in[5];
    const float* conv_b = (const float*)d_in[6];
    const float* W_xp   = (const float*)d_in[7];
    const float* W_dt   = (const float*)d_in[8];
    const float* b_dt   = (const float*)d_in[9];
    const float* Wr     = (const float*)d_in[10];
    const float* br     = (const float*)d_in[11];
    const float* W_out  = (const float*)d_in[12];
    float* out = (float*)d_out;

    gemm_xz<<<dim3(16, 16), 128>>>(x, ln_w, ln_b, W_in, conv_w, adj, W_out);
    gemm_conv<<<dim3(8, 16), 128>>>(conv_b);
    ssm_deg<<<1024, 128>>>(W_xp, W_dt, b_dt, adj);
    scan_kernel<<<1024, 128>>>(Wr, br);
    gemm_out<<<dim3(4, 16), 128>>>(x, out);
}